// round 1
// baseline (speedup 1.0000x reference)
#include <cuda_runtime.h>
#include <cuda_bf16.h>

// MHC layer: B=8192, N=4, C=4096, f32.
// out[b,i,c] = sum_j P[i][j]*x[b,j,c] + 2*sigmoid(H_post[i]) * y_norm[b,c]
// where y_norm = RMSNorm_w( bf16_roundtrip( sum_n sigmoid(H_pre[n])*x[b,n,c] ) )
// and P = Sinkhorn_3(exp(H_res)) (4x4, doubly-stochastic-ish).
//
// Strategy: one CTA per b. x row (4*4096 f32 = 64KB) held in registers,
// read once, written once. HBM-bound; everything else fused.

#define C_DIM 4096
#define NS 4
#define THREADS 512
#define VEC 2               // float4 chunks per thread per stream: 4096/4/512
#define EPS 1e-6f

__global__ __launch_bounds__(THREADS, 1)
void mhc_kernel(const float* __restrict__ x,
                const float* __restrict__ w,
                const float* __restrict__ H_pre,
                const float* __restrict__ H_post,
                const float* __restrict__ H_res,
                float* __restrict__ out)
{
    const int b = blockIdx.x;
    const int t = threadIdx.x;

    // ---- tiny parameter math (redundant per thread; negligible) ----
    float hpre[NS], hpost[NS];
#pragma unroll
    for (int n = 0; n < NS; n++) {
        hpre[n]  = 1.0f / (1.0f + expf(-__ldg(&H_pre[n])));
        hpost[n] = 2.0f / (1.0f + expf(-__ldg(&H_post[n])));
    }
    float P[NS][NS];
#pragma unroll
    for (int i = 0; i < NS; i++)
#pragma unroll
        for (int j = 0; j < NS; j++)
            P[i][j] = expf(__ldg(&H_res[i * NS + j]));
#pragma unroll
    for (int it = 0; it < 3; it++) {
#pragma unroll
        for (int i = 0; i < NS; i++) {
            float rs = P[i][0] + P[i][1] + P[i][2] + P[i][3];
            float inv = 1.0f / (rs + EPS);
#pragma unroll
            for (int j = 0; j < NS; j++) P[i][j] *= inv;
        }
#pragma unroll
        for (int j = 0; j < NS; j++) {
            float cs = P[0][j] + P[1][j] + P[2][j] + P[3][j];
            float inv = 1.0f / (cs + EPS);
#pragma unroll
            for (int i = 0; i < NS; i++) P[i][j] *= inv;
        }
    }

    // ---- load x[b, :, :] into registers (read once) ----
    const float4* __restrict__ xr =
        reinterpret_cast<const float4*>(x + (size_t)b * NS * C_DIM);
    float4 v[NS][VEC];
#pragma unroll
    for (int n = 0; n < NS; n++)
#pragma unroll
        for (int k = 0; k < VEC; k++)
            v[n][k] = xr[n * (C_DIM / 4) + t + k * THREADS];

    // ---- sigmoid-gated stream aggregation + bf16 round-trip ----
    float4 agg[VEC];
    float ss = 0.0f;
#pragma unroll
    for (int k = 0; k < VEC; k++) {
        float ax = hpre[0]*v[0][k].x + hpre[1]*v[1][k].x + hpre[2]*v[2][k].x + hpre[3]*v[3][k].x;
        float ay = hpre[0]*v[0][k].y + hpre[1]*v[1][k].y + hpre[2]*v[2][k].y + hpre[3]*v[3][k].y;
        float az = hpre[0]*v[0][k].z + hpre[1]*v[1][k].z + hpre[2]*v[2][k].z + hpre[3]*v[3][k].z;
        float aw = hpre[0]*v[0][k].w + hpre[1]*v[1][k].w + hpre[2]*v[2][k].w + hpre[3]*v[3][k].w;
        // bf16 round-trip (RN), matching jnp astype(bfloat16).astype(float32)
        ax = __bfloat162float(__float2bfloat16(ax));
        ay = __bfloat162float(__float2bfloat16(ay));
        az = __bfloat162float(__float2bfloat16(az));
        aw = __bfloat162float(__float2bfloat16(aw));
        agg[k].x = ax; agg[k].y = ay; agg[k].z = az; agg[k].w = aw;
        ss += ax*ax + ay*ay + az*az + aw*aw;
    }

    // ---- block reduction of sum of squares (16 warps) ----
    __shared__ float red[THREADS / 32];
#pragma unroll
    for (int off = 16; off > 0; off >>= 1)
        ss += __shfl_xor_sync(0xFFFFFFFFu, ss, off);
    if ((t & 31) == 0) red[t >> 5] = ss;
    __syncthreads();
    if (t < 32) {
        float s = (t < THREADS / 32) ? red[t] : 0.0f;
#pragma unroll
        for (int off = 8; off > 0; off >>= 1)
            s += __shfl_xor_sync(0xFFFFFFFFu, s, off);
        if (t == 0) red[0] = s;
    }
    __syncthreads();
    const float inv_rms = rsqrtf(red[0] * (1.0f / C_DIM) + EPS);

    // ---- epilogue: y_norm, 4x4 mix, gated add, single write ----
    const float4* __restrict__ wr = reinterpret_cast<const float4*>(w);
    float4* __restrict__ outr =
        reinterpret_cast<float4*>(out + (size_t)b * NS * C_DIM);
#pragma unroll
    for (int k = 0; k < VEC; k++) {
        const float4 w4 = wr[t + k * THREADS];
        float yx = agg[k].x * inv_rms * w4.x;
        float yy = agg[k].y * inv_rms * w4.y;
        float yz = agg[k].z * inv_rms * w4.z;
        float yw = agg[k].w * inv_rms * w4.w;
#pragma unroll
        for (int i = 0; i < NS; i++) {
            float4 o;
            o.x = P[i][0]*v[0][k].x + P[i][1]*v[1][k].x + P[i][2]*v[2][k].x + P[i][3]*v[3][k].x + hpost[i]*yx;
            o.y = P[i][0]*v[0][k].y + P[i][1]*v[1][k].y + P[i][2]*v[2][k].y + P[i][3]*v[3][k].y + hpost[i]*yy;
            o.z = P[i][0]*v[0][k].z + P[i][1]*v[1][k].z + P[i][2]*v[2][k].z + P[i][3]*v[3][k].z + hpost[i]*yz;
            o.w = P[i][0]*v[0][k].w + P[i][1]*v[1][k].w + P[i][2]*v[2][k].w + P[i][3]*v[3][k].w + hpost[i]*yw;
            outr[i * (C_DIM / 4) + t + k * THREADS] = o;
        }
    }
}

extern "C" void kernel_launch(void* const* d_in, const int* in_sizes, int n_in,
                              void* d_out, int out_size)
{
    const float* x      = (const float*)d_in[0];  // [8192, 4, 4096]
    const float* w      = (const float*)d_in[1];  // [4096]
    const float* H_pre  = (const float*)d_in[2];  // [4]
    const float* H_post = (const float*)d_in[3];  // [4]
    const float* H_res  = (const float*)d_in[4];  // [4, 4]
    float* out = (float*)d_out;                   // [8192, 4, 4096]

    const int B = in_sizes[0] / (NS * C_DIM);     // 8192
    mhc_kernel<<<B, THREADS>>>(x, w, H_pre, H_post, H_res, out);
}

// round 2
// speedup vs baseline: 1.6805x; 1.6805x over previous
#include <cuda_runtime.h>
#include <cuda_bf16.h>
#include <cstdint>

// MHC layer: B=8192, N=4, C=4096, f32. HBM-bound fusion.
// R2: x staged in SMEM via cp.async (no register residency) -> regs ~60 ->
// 2 CTAs/SM -> load/reduce/store phases of neighboring CTAs overlap.

#define C_DIM 4096
#define NS 4
#define THREADS 512
#define VEC 2               // float4 chunks per thread per stream: 4096/4/512
#define EPS 1e-6f
#define SMEM_BYTES (NS * C_DIM * 4)   // 64 KB: x row as float4[4][1024]

__device__ __forceinline__ uint32_t smem_u32(const void* p) {
    uint32_t a;
    asm("{ .reg .u64 t; cvta.to.shared.u64 t, %1; cvt.u32.u64 %0, t; }"
        : "=r"(a) : "l"(p));
    return a;
}

__global__ __launch_bounds__(THREADS, 2)
void mhc_kernel(const float* __restrict__ x,
                const float* __restrict__ w,
                const float* __restrict__ H_pre,
                const float* __restrict__ H_post,
                const float* __restrict__ H_res,
                float* __restrict__ out)
{
    extern __shared__ float4 sx[];          // [NS * C_DIM/4] = [4096] float4
    __shared__ float red[THREADS / 32];

    const int b = blockIdx.x;
    const int t = threadIdx.x;

    // ---- kick off async copy of x[b,:,:] into smem (bypasses RF) ----
    const float4* __restrict__ xr =
        reinterpret_cast<const float4*>(x + (size_t)b * NS * C_DIM);
    {
        const uint32_t sbase = smem_u32(sx);
#pragma unroll
        for (int n = 0; n < NS; n++)
#pragma unroll
            for (int k = 0; k < VEC; k++) {
                const int idx = n * (C_DIM / 4) + t + k * THREADS;
                asm volatile("cp.async.cg.shared.global [%0], [%1], 16;"
                             :: "r"(sbase + idx * 16), "l"(xr + idx));
            }
        asm volatile("cp.async.commit_group;");
    }

    // ---- tiny parameter math while copies are in flight ----
    float hpre[NS], hpost[NS];
#pragma unroll
    for (int n = 0; n < NS; n++) {
        hpre[n]  = 1.0f / (1.0f + expf(-__ldg(&H_pre[n])));
        hpost[n] = 2.0f / (1.0f + expf(-__ldg(&H_post[n])));
    }
    float P[NS][NS];
#pragma unroll
    for (int i = 0; i < NS; i++)
#pragma unroll
        for (int j = 0; j < NS; j++)
            P[i][j] = expf(__ldg(&H_res[i * NS + j]));
#pragma unroll
    for (int it = 0; it < 3; it++) {
#pragma unroll
        for (int i = 0; i < NS; i++) {
            float inv = 1.0f / (P[i][0] + P[i][1] + P[i][2] + P[i][3] + EPS);
#pragma unroll
            for (int j = 0; j < NS; j++) P[i][j] *= inv;
        }
#pragma unroll
        for (int j = 0; j < NS; j++) {
            float inv = 1.0f / (P[0][j] + P[1][j] + P[2][j] + P[3][j] + EPS);
#pragma unroll
            for (int i = 0; i < NS; i++) P[i][j] *= inv;
        }
    }

    asm volatile("cp.async.wait_group 0;" ::: "memory");
    __syncthreads();

    // ---- pass A: gated aggregation + bf16 round-trip + sum of squares ----
    float4 agg[VEC];
    float ss = 0.0f;
#pragma unroll
    for (int k = 0; k < VEC; k++) {
        const int c4 = t + k * THREADS;
        const float4 v0 = sx[0 * (C_DIM / 4) + c4];
        const float4 v1 = sx[1 * (C_DIM / 4) + c4];
        const float4 v2 = sx[2 * (C_DIM / 4) + c4];
        const float4 v3 = sx[3 * (C_DIM / 4) + c4];
        float ax = hpre[0]*v0.x + hpre[1]*v1.x + hpre[2]*v2.x + hpre[3]*v3.x;
        float ay = hpre[0]*v0.y + hpre[1]*v1.y + hpre[2]*v2.y + hpre[3]*v3.y;
        float az = hpre[0]*v0.z + hpre[1]*v1.z + hpre[2]*v2.z + hpre[3]*v3.z;
        float aw = hpre[0]*v0.w + hpre[1]*v1.w + hpre[2]*v2.w + hpre[3]*v3.w;
        ax = __bfloat162float(__float2bfloat16(ax));
        ay = __bfloat162float(__float2bfloat16(ay));
        az = __bfloat162float(__float2bfloat16(az));
        aw = __bfloat162float(__float2bfloat16(aw));
        agg[k].x = ax; agg[k].y = ay; agg[k].z = az; agg[k].w = aw;
        ss += ax*ax + ay*ay + az*az + aw*aw;
    }

    // ---- block reduce sum of squares ----
#pragma unroll
    for (int off = 16; off > 0; off >>= 1)
        ss += __shfl_xor_sync(0xFFFFFFFFu, ss, off);
    if ((t & 31) == 0) red[t >> 5] = ss;
    __syncthreads();
    if (t < 32) {
        float s = (t < THREADS / 32) ? red[t] : 0.0f;
#pragma unroll
        for (int off = 8; off > 0; off >>= 1)
            s += __shfl_xor_sync(0xFFFFFFFFu, s, off);
        if (t == 0) red[0] = s;
    }
    __syncthreads();
    const float inv_rms = rsqrtf(red[0] * (1.0f / C_DIM) + EPS);

    // ---- pass B: 4x4 mix + gated RMSNorm residual, single write ----
    const float4* __restrict__ wr = reinterpret_cast<const float4*>(w);
    float4* __restrict__ outr =
        reinterpret_cast<float4*>(out + (size_t)b * NS * C_DIM);
#pragma unroll
    for (int k = 0; k < VEC; k++) {
        const int c4 = t + k * THREADS;
        const float4 v0 = sx[0 * (C_DIM / 4) + c4];
        const float4 v1 = sx[1 * (C_DIM / 4) + c4];
        const float4 v2 = sx[2 * (C_DIM / 4) + c4];
        const float4 v3 = sx[3 * (C_DIM / 4) + c4];
        const float4 w4 = wr[c4];
        const float yx = agg[k].x * inv_rms * w4.x;
        const float yy = agg[k].y * inv_rms * w4.y;
        const float yz = agg[k].z * inv_rms * w4.z;
        const float yw = agg[k].w * inv_rms * w4.w;
#pragma unroll
        for (int i = 0; i < NS; i++) {
            float4 o;
            o.x = P[i][0]*v0.x + P[i][1]*v1.x + P[i][2]*v2.x + P[i][3]*v3.x + hpost[i]*yx;
            o.y = P[i][0]*v0.y + P[i][1]*v1.y + P[i][2]*v2.y + P[i][3]*v3.y + hpost[i]*yy;
            o.z = P[i][0]*v0.z + P[i][1]*v1.z + P[i][2]*v2.z + P[i][3]*v3.z + hpost[i]*yz;
            o.w = P[i][0]*v0.w + P[i][1]*v1.w + P[i][2]*v2.w + P[i][3]*v3.w + hpost[i]*yw;
            outr[i * (C_DIM / 4) + c4] = o;
        }
    }
}

extern "C" void kernel_launch(void* const* d_in, const int* in_sizes, int n_in,
                              void* d_out, int out_size)
{
    const float* x      = (const float*)d_in[0];  // [8192, 4, 4096]
    const float* w      = (const float*)d_in[1];  // [4096]
    const float* H_pre  = (const float*)d_in[2];  // [4]
    const float* H_post = (const float*)d_in[3];  // [4]
    const float* H_res  = (const float*)d_in[4];  // [4, 4]
    float* out = (float*)d_out;                   // [8192, 4, 4096]

    cudaFuncSetAttribute(mhc_kernel,
                         cudaFuncAttributeMaxDynamicSharedMemorySize, SMEM_BYTES);

    const int B = in_sizes[0] / (NS * C_DIM);     // 8192
    mhc_kernel<<<B, THREADS, SMEM_BYTES>>>(x, w, H_pre, H_post, H_res, out);
}